// round 15
// baseline (speedup 1.0000x reference)
#include <cuda_runtime.h>
#include <cstdint>

// Yolo_Loss: S=56, B=5, C=20, N=128.
// predicts: [N,S,S,B,25] f32, targets: [N,S,S,25] f32, anchors: [5,2] f32.
// R14 (best: 39.4us, DRAM 80.3%) + DYNAMIC TILE STEALING: tid0 pulls the next
// 128-cell tile index from a global counter, so all 148 CTAs stream until the
// pool empties (kills the 21-vs-22 static tail + per-CTA spread). Fixed-point
// packed u64 RED epilogue is order-independent -> bit-exact under stealing.
// No gpu-scope fences anywhere (they drain in-flight TMA on sm_103a: R5/R6).

#define S_DIM 56
#define N_IMG 128
#define B_BOX 5
#define C_CLS 20
#define CVEC  25
#define CELLS (N_IMG * S_DIM * S_DIM)   // 401408
#define TILE_CELLS 128
#define THREADS    128
#define NTILES (CELLS / TILE_CELLS)     // 3136 (exact)
#define GRID   148                      // 1 CTA per SM, single wave

#define TILE_P (TILE_CELLS * CVEC * B_BOX)  // 16000 floats
#define TILE_T (TILE_CELLS * CVEC)          //  3200 floats
#define TILE_F (TILE_P + TILE_T)            // 19200 floats per buffer
#define TPB    (TILE_P * 4)                 // 64000 B
#define TTB    (TILE_T * 4)                 // 12800 B
#define TILE_BYTES (TPB + TTB)              // 76800 B
#define SMEM_BYTES (2 * TILE_BYTES)         // 153600 B dynamic smem

#define FIX_SCALE 262144.0                  // 2^18
#define CNT_SHIFT 44
#define SUM_MASK  ((1ULL << CNT_SHIFT) - 1ULL)

__device__ unsigned long long g_acc  = 0ULL;
__device__ int                g_tile = 0;

__device__ __forceinline__ float sigmoid_f(float x) {
    float t;
    asm("tanh.approx.f32 %0, %1;" : "=f"(t) : "f"(x * 0.5f));
    return fmaf(0.5f, t, 0.5f);
}

__device__ __forceinline__ uint32_t smem_u32(const void* p) {
    return (uint32_t)__cvta_generic_to_shared(p);
}

__device__ __forceinline__ void mbar_wait(uint32_t mbar_a, uint32_t parity) {
    uint32_t done;
    asm volatile(
        "{\n\t.reg .pred p;\n\t"
        "mbarrier.try_wait.parity.acquire.cta.shared::cta.b64 p, [%1], %2;\n\t"
        "selp.b32 %0, 1, 0, p;\n\t}"
        : "=r"(done) : "r"(mbar_a), "r"(parity) : "memory");
    if (!done) {
        asm volatile(
            "{\n\t.reg .pred P1;\n\t"
            "WAIT_LOOP_%=:\n\t"
            "mbarrier.try_wait.parity.acquire.cta.shared::cta.b64 P1, [%0], %1, 0x989680;\n\t"
            "@P1 bra.uni WAIT_DONE_%=;\n\t"
            "bra.uni WAIT_LOOP_%=;\n\t"
            "WAIT_DONE_%=:\n\t}"
            :: "r"(mbar_a), "r"(parity) : "memory");
    }
}

__global__ __launch_bounds__(THREADS) void yolo_loss_kernel(
    const float* __restrict__ gp,
    const float* __restrict__ gt,
    const float* __restrict__ ga,
    float* __restrict__ out)
{
    extern __shared__ __align__(128) float sm[];          // 2 buffers of TILE_F floats
    __shared__ __align__(8) unsigned long long mbar[2];
    __shared__ int   tile_of[2];                          // tile id per buffer, -1 = none
    __shared__ float wsum[THREADS / 32];

    const int tid = threadIdx.x;
    const uint32_t mb0 = smem_u32(&mbar[0]);
    const uint32_t mb1 = smem_u32(&mbar[1]);

    if (tid == 0) {
        asm volatile("mbarrier.init.shared.b64 [%0], 1;" :: "r"(mb0) : "memory");
        asm volatile("mbarrier.init.shared.b64 [%0], 1;" :: "r"(mb1) : "memory");
    }
    __syncthreads();

    // ---- TMA issue helper (tid 0 only): tile t -> buffer b ----
    auto issue = [&](int t, int b) {
        const uint32_t mba = b ? mb1 : mb0;
        asm volatile("mbarrier.arrive.expect_tx.shared.b64 _, [%0], %1;"
                     :: "r"(mba), "r"((uint32_t)TILE_BYTES) : "memory");
        const char* srcp = (const char*)(gp + (size_t)t * TILE_P);
        const char* srct = (const char*)(gt + (size_t)t * TILE_T);
        const uint32_t dst = smem_u32(sm + b * TILE_F);
        asm volatile(
            "cp.async.bulk.shared::cta.global.mbarrier::complete_tx::bytes [%0], [%1], %2, [%3];"
            :: "r"(dst), "l"(srcp), "r"((uint32_t)TPB), "r"(mba) : "memory");
        asm volatile(
            "cp.async.bulk.shared::cta.global.mbarrier::complete_tx::bytes [%0], [%1], %2, [%3];"
            :: "r"(dst + TPB), "l"(srct), "r"((uint32_t)TTB), "r"(mba) : "memory");
    };

    // ---- Prefetch: steal two tiles ----
    if (tid == 0) {
        int t0 = atomicAdd(&g_tile, 1);
        tile_of[0] = (t0 < NTILES) ? t0 : -1;
        if (t0 < NTILES) issue(t0, 0);
        int t1 = atomicAdd(&g_tile, 1);
        tile_of[1] = (t1 < NTILES) ? t1 : -1;
        if (t1 < NTILES) issue(t1, 1);
    }
    __syncthreads();

    // anchors: tiny, read once into registers
    float anc[2 * B_BOX];
#pragma unroll
    for (int i = 0; i < 2 * B_BOX; ++i) anc[i] = __ldg(ga + i);

    float loss = 0.0f;
    uint32_t ph[2] = {0u, 0u};
    int b = 0;

    while (tile_of[b] >= 0) {
        mbar_wait(b ? mb1 : mb0, ph[b]);
        ph[b] ^= 1u;

        const float* sp = sm + b * TILE_F;
        const float* st = sp + TILE_P;
        const float* pc = sp + tid * (CVEC * B_BOX);   // stride 125: conflict-free
        const float* tc = st + tid * CVEC;             // stride 25:  conflict-free

        const float e   = tc[C_CLS];
        const float tcx = tc[C_CLS + 1], tcy = tc[C_CLS + 2];
        const float tw  = tc[C_CLS + 3], th  = tc[C_CLS + 4];
        const float tx1 = tcx - 0.5f * tw, ty1 = tcy - 0.5f * th;
        const float tx2 = tcx + 0.5f * tw, ty2 = tcy + 0.5f * th;
        const float area_t = tw * th;

        float bnum = -1.0f, bden = 1.0f;
        int   bidx = 0;
        float bsx = 0.f, bsy = 0.f, bw = 0.f, bh = 0.f;

#pragma unroll
        for (int bb = 0; bb < B_BOX; ++bb) {
            const float* pb = pc + bb * CVEC;
            const float sx = sigmoid_f(pb[C_CLS + 1]);
            const float sy = sigmoid_f(pb[C_CLS + 2]);
            const float w  = __expf(pb[C_CLS + 3]) * anc[2 * bb];
            const float h  = __expf(pb[C_CLS + 4]) * anc[2 * bb + 1];

            const float x1 = sx - 0.5f * w, y1 = sy - 0.5f * h;
            const float x2 = sx + 0.5f * w, y2 = sy + 0.5f * h;
            const float lx = fmaxf(x1, tx1), ly = fmaxf(y1, ty1);
            const float rx = fminf(x2, tx2), ry = fminf(y2, ty2);
            const float wi = fmaxf(rx - lx, 0.0f);
            const float hi = fmaxf(ry - ly, 0.0f);
            const float inter = wi * hi;
            const float den   = fmaf(w, h, area_t) - inter;

            if (inter * bden > bnum * den) {   // strict > == first-max argmax
                bidx = bb; bnum = inter; bden = den;
                bsx = sx; bsy = sy; bw = w; bh = h;
            }
        }

        const float e2 = e * e;

        const float dx = bsx - tcx, dy = bsy - tcy;
        float l = e2 * (dx * dx + dy * dy);

        const float pw = (bw > 0.f) ? sqrtf(bw + 1e-6f)
                                    : ((bw < 0.f) ? -sqrtf(-bw + 1e-6f) : 0.f);
        const float ph2 = (bh > 0.f) ? sqrtf(bh + 1e-6f)
                                     : ((bh < 0.f) ? -sqrtf(-bh + 1e-6f) : 0.f);
        const float dw = pw - tw, dh = ph2 - th;
        l += e2 * (dw * dw + dh * dh);

        const float* pbest = pc + bidx * CVEC;
        const float fbidx = (float)bidx;
        float cls = 0.0f;
#pragma unroll
        for (int c = 0; c < C_CLS; ++c) {
            float pv = pbest[c];
            if (c == 0) pv *= fbidx;
            const float d = pv - tc[c];
            cls = fmaf(d, d, cls);
        }
        l += e2 * cls;

        const float dobj   = pbest[C_CLS] - e;
        const float one_me = 1.0f - e;
        l += (e2 + one_me * one_me) * dobj * dobj;

        loss += l;

        __syncthreads();                      // all readers done with buffer b
        if (tid == 0) {                       // steal + refill buffer b
            int t = atomicAdd(&g_tile, 1);
            tile_of[b] = (t < NTILES) ? t : -1;
            if (t < NTILES) issue(t, b);
        }
        __syncthreads();                      // tile_of[b] visible to all
        b ^= 1;
    }

    // ---- CTA reduction ----
#pragma unroll
    for (int o = 16; o; o >>= 1)
        loss += __shfl_xor_sync(0xffffffffu, loss, o);
    if ((tid & 31) == 0) wsum[tid >> 5] = loss;
    __syncthreads();

    // ---- Grid completion: fire-and-forget packed RED + last-CTA spinner ----
    if (tid == 0) {
        float s = 0.0f;
#pragma unroll
        for (int i = 0; i < THREADS / 32; ++i) s += wsum[i];

        const unsigned long long fx =
            (unsigned long long)__double2ll_rn((double)s * FIX_SCALE);
        const unsigned long long contrib = fx + (1ULL << CNT_SHIFT);
        asm volatile("red.relaxed.gpu.global.add.u64 [%0], %1;"
                     :: "l"(&g_acc), "l"(contrib) : "memory");

        if (blockIdx.x == GRID - 1) {
            unsigned long long cur;
            for (;;) {
                asm volatile("ld.relaxed.gpu.global.u64 %0, [%1];"
                             : "=l"(cur) : "l"(&g_acc) : "memory");
                if ((cur >> CNT_SHIFT) == (unsigned long long)GRID) break;
                __nanosleep(128);
            }
            *out = (float)((double)(cur & SUM_MASK) * (1.0 / FIX_SCALE));
            // All CTAs have finished stealing (their REDs happen after loop
            // exit), so resetting the pool + accumulator here is safe.
            asm volatile("st.relaxed.gpu.global.u64 [%0], %1;"
                         :: "l"(&g_acc), "l"(0ULL) : "memory");
            asm volatile("st.relaxed.gpu.global.s32 [%0], %1;"
                         :: "l"(&g_tile), "r"(0) : "memory");
        }
    }
}

extern "C" void kernel_launch(void* const* d_in, const int* in_sizes, int n_in,
                              void* d_out, int out_size)
{
    const float* p = (const float*)d_in[0];
    const float* t = (const float*)d_in[1];
    const float* a = (const float*)d_in[2];
    float* out = (float*)d_out;

    cudaFuncSetAttribute(yolo_loss_kernel,
                         cudaFuncAttributeMaxDynamicSharedMemorySize, SMEM_BYTES);

    yolo_loss_kernel<<<GRID, THREADS, SMEM_BYTES>>>(p, t, a, out);
}

// round 16
// speedup vs baseline: 1.0188x; 1.0188x over previous
#include <cuda_runtime.h>
#include <cstdint>

// Yolo_Loss: S=56, B=5, C=20, N=128.
// predicts: [N,S,S,B,25] f32, targets: [N,S,S,25] f32, anchors: [5,2] f32.
// R14 champion (39.4us, DRAM 80.3%: persistent 148, double-buffered one-shot
// TMA 128-cell tiles, packed-u64 RED + spinner, zero fences) + HYBRID TAIL
// BALANCING: 21 static tiles/CTA; the 28 remainder tiles live in a steal pool
// tapped by ONE atomic per CTA inside the k=19 refill slot (hidden under
// compute). Ahead-CTAs grab the extras -> no 21-vs-22 static tail. R15 showed
// per-tile steal atomics cost ~4.7us; this does ONE per CTA total.

#define S_DIM 56
#define N_IMG 128
#define B_BOX 5
#define C_CLS 20
#define CVEC  25
#define CELLS (N_IMG * S_DIM * S_DIM)   // 401408
#define TILE_CELLS 128
#define THREADS    128
#define NTILES (CELLS / TILE_CELLS)     // 3136
#define GRID   148                      // 1 CTA per SM, single wave
#define NT_STATIC (NTILES / GRID)       // 21
#define POOL_BASE (GRID * NT_STATIC)    // 3108
#define POOL_N    (NTILES - POOL_BASE)  // 28

#define TILE_P (TILE_CELLS * CVEC * B_BOX)  // 16000 floats
#define TILE_T (TILE_CELLS * CVEC)          //  3200 floats
#define TILE_F (TILE_P + TILE_T)            // 19200 floats per buffer
#define TPB    (TILE_P * 4)                 // 64000 B
#define TTB    (TILE_T * 4)                 // 12800 B
#define TILE_BYTES (TPB + TTB)              // 76800 B
#define SMEM_BYTES (2 * TILE_BYTES)         // 153600 B dynamic smem

#define FIX_SCALE 262144.0                  // 2^18
#define CNT_SHIFT 44
#define SUM_MASK  ((1ULL << CNT_SHIFT) - 1ULL)

__device__ unsigned long long g_acc  = 0ULL;
__device__ int                g_pool = 0;

__device__ __forceinline__ float sigmoid_f(float x) {
    float t;
    asm("tanh.approx.f32 %0, %1;" : "=f"(t) : "f"(x * 0.5f));
    return fmaf(0.5f, t, 0.5f);
}

__device__ __forceinline__ uint32_t smem_u32(const void* p) {
    return (uint32_t)__cvta_generic_to_shared(p);
}

__device__ __forceinline__ void mbar_wait(uint32_t mbar_a, uint32_t parity) {
    uint32_t done;
    asm volatile(
        "{\n\t.reg .pred p;\n\t"
        "mbarrier.try_wait.parity.acquire.cta.shared::cta.b64 p, [%1], %2;\n\t"
        "selp.b32 %0, 1, 0, p;\n\t}"
        : "=r"(done) : "r"(mbar_a), "r"(parity) : "memory");
    if (!done) {
        asm volatile(
            "{\n\t.reg .pred P1;\n\t"
            "WAIT_LOOP_%=:\n\t"
            "mbarrier.try_wait.parity.acquire.cta.shared::cta.b64 P1, [%0], %1, 0x989680;\n\t"
            "@P1 bra.uni WAIT_DONE_%=;\n\t"
            "bra.uni WAIT_LOOP_%=;\n\t"
            "WAIT_DONE_%=:\n\t}"
            :: "r"(mbar_a), "r"(parity) : "memory");
    }
}

__global__ __launch_bounds__(THREADS) void yolo_loss_kernel(
    const float* __restrict__ gp,
    const float* __restrict__ gt,
    const float* __restrict__ ga,
    float* __restrict__ out)
{
    extern __shared__ __align__(128) float sm[];          // 2 buffers of TILE_F floats
    __shared__ __align__(8) unsigned long long mbar[2];
    __shared__ int   nt_sm;
    __shared__ float wsum[THREADS / 32];

    const int tid = threadIdx.x;
    const int bid = blockIdx.x;
    const uint32_t mb0 = smem_u32(&mbar[0]);
    const uint32_t mb1 = smem_u32(&mbar[1]);

    if (tid == 0) {
        asm volatile("mbarrier.init.shared.b64 [%0], 1;" :: "r"(mb0) : "memory");
        asm volatile("mbarrier.init.shared.b64 [%0], 1;" :: "r"(mb1) : "memory");
        nt_sm = NT_STATIC;
    }
    __syncthreads();

    // ---- TMA issue helper (tid 0 only): tile t -> buffer b ----
    auto issue = [&](int t, int b) {
        const uint32_t mba = b ? mb1 : mb0;
        asm volatile("mbarrier.arrive.expect_tx.shared.b64 _, [%0], %1;"
                     :: "r"(mba), "r"((uint32_t)TILE_BYTES) : "memory");
        const char* srcp = (const char*)(gp + (size_t)t * TILE_P);
        const char* srct = (const char*)(gt + (size_t)t * TILE_T);
        const uint32_t dst = smem_u32(sm + b * TILE_F);
        asm volatile(
            "cp.async.bulk.shared::cta.global.mbarrier::complete_tx::bytes [%0], [%1], %2, [%3];"
            :: "r"(dst), "l"(srcp), "r"((uint32_t)TPB), "r"(mba) : "memory");
        asm volatile(
            "cp.async.bulk.shared::cta.global.mbarrier::complete_tx::bytes [%0], [%1], %2, [%3];"
            :: "r"(dst + TPB), "l"(srct), "r"((uint32_t)TTB), "r"(mba) : "memory");
    };

    if (tid == 0) {
        issue(bid, 0);                  // static tile k=0
        issue(bid + GRID, 1);           // static tile k=1   (NT_STATIC >= 2)
    }

    // anchors: tiny, read once into registers
    float anc[2 * B_BOX];
#pragma unroll
    for (int i = 0; i < 2 * B_BOX; ++i) anc[i] = __ldg(ga + i);

    float loss = 0.0f;
    uint32_t ph[2] = {0u, 0u};
    int nt = NT_STATIC;

    for (int k = 0; k < nt; ++k) {
        const int b = k & 1;
        mbar_wait(b ? mb1 : mb0, ph[b]);
        ph[b] ^= 1u;

        const float* sp = sm + b * TILE_F;
        const float* st = sp + TILE_P;
        const float* pc = sp + tid * (CVEC * B_BOX);   // stride 125: conflict-free
        const float* tc = st + tid * CVEC;             // stride 25:  conflict-free

        const float e   = tc[C_CLS];
        const float tcx = tc[C_CLS + 1], tcy = tc[C_CLS + 2];
        const float tw  = tc[C_CLS + 3], th  = tc[C_CLS + 4];
        const float tx1 = tcx - 0.5f * tw, ty1 = tcy - 0.5f * th;
        const float tx2 = tcx + 0.5f * tw, ty2 = tcy + 0.5f * th;
        const float area_t = tw * th;

        float bnum = -1.0f, bden = 1.0f;
        int   bidx = 0;
        float bsx = 0.f, bsy = 0.f, bw = 0.f, bh = 0.f;

#pragma unroll
        for (int bb = 0; bb < B_BOX; ++bb) {
            const float* pb = pc + bb * CVEC;
            const float sx = sigmoid_f(pb[C_CLS + 1]);
            const float sy = sigmoid_f(pb[C_CLS + 2]);
            const float w  = __expf(pb[C_CLS + 3]) * anc[2 * bb];
            const float h  = __expf(pb[C_CLS + 4]) * anc[2 * bb + 1];

            const float x1 = sx - 0.5f * w, y1 = sy - 0.5f * h;
            const float x2 = sx + 0.5f * w, y2 = sy + 0.5f * h;
            const float lx = fmaxf(x1, tx1), ly = fmaxf(y1, ty1);
            const float rx = fminf(x2, tx2), ry = fminf(y2, ty2);
            const float wi = fmaxf(rx - lx, 0.0f);
            const float hi = fmaxf(ry - ly, 0.0f);
            const float inter = wi * hi;
            const float den   = fmaf(w, h, area_t) - inter;

            if (inter * bden > bnum * den) {   // strict > == first-max argmax
                bidx = bb; bnum = inter; bden = den;
                bsx = sx; bsy = sy; bw = w; bh = h;
            }
        }

        const float e2 = e * e;

        const float dx = bsx - tcx, dy = bsy - tcy;
        float l = e2 * (dx * dx + dy * dy);

        const float pw = (bw > 0.f) ? sqrtf(bw + 1e-6f)
                                    : ((bw < 0.f) ? -sqrtf(-bw + 1e-6f) : 0.f);
        const float ph2 = (bh > 0.f) ? sqrtf(bh + 1e-6f)
                                     : ((bh < 0.f) ? -sqrtf(-bh + 1e-6f) : 0.f);
        const float dw = pw - tw, dh = ph2 - th;
        l += e2 * (dw * dw + dh * dh);

        const float* pbest = pc + bidx * CVEC;
        const float fbidx = (float)bidx;
        float cls = 0.0f;
#pragma unroll
        for (int c = 0; c < C_CLS; ++c) {
            float pv = pbest[c];
            if (c == 0) pv *= fbidx;
            const float d = pv - tc[c];
            cls = fmaf(d, d, cls);
        }
        l += e2 * cls;

        const float dobj   = pbest[C_CLS] - e;
        const float one_me = 1.0f - e;
        l += (e2 + one_me * one_me) * dobj * dobj;

        loss += l;

        __syncthreads();                      // all readers done with buffer b
        if (tid == 0) {
            const int kk = k + 2;
            if (kk < NT_STATIC) {
                issue(bid + kk * GRID, kk & 1);        // static refill
            } else if (kk == NT_STATIC) {
                // ONE steal for the whole kernel, hidden in this refill slot:
                // ahead-CTAs reach here first and grab a remainder tile.
                const int pi = atomicAdd(&g_pool, 1);
                if (pi < POOL_N) {
                    nt_sm = NT_STATIC + 1;
                    issue(POOL_BASE + pi, kk & 1);
                }
            }
        }
        if (k == NT_STATIC - 2) {             // one-time extra sync: publish nt
            __syncthreads();
            nt = nt_sm;
        }
    }

    // ---- CTA reduction ----
#pragma unroll
    for (int o = 16; o; o >>= 1)
        loss += __shfl_xor_sync(0xffffffffu, loss, o);
    if ((tid & 31) == 0) wsum[tid >> 5] = loss;
    __syncthreads();

    // ---- Grid completion: fire-and-forget packed RED + last-CTA spinner ----
    if (tid == 0) {
        float s = 0.0f;
#pragma unroll
        for (int i = 0; i < THREADS / 32; ++i) s += wsum[i];

        const unsigned long long fx =
            (unsigned long long)__double2ll_rn((double)s * FIX_SCALE);
        const unsigned long long contrib = fx + (1ULL << CNT_SHIFT);
        asm volatile("red.relaxed.gpu.global.add.u64 [%0], %1;"
                     :: "l"(&g_acc), "l"(contrib) : "memory");

        if (blockIdx.x == GRID - 1) {
            unsigned long long cur;
            for (;;) {
                asm volatile("ld.relaxed.gpu.global.u64 %0, [%1];"
                             : "=l"(cur) : "l"(&g_acc) : "memory");
                if ((cur >> CNT_SHIFT) == (unsigned long long)GRID) break;
                __nanosleep(128);
            }
            *out = (float)((double)(cur & SUM_MASK) * (1.0 / FIX_SCALE));
            // Every CTA's pool atomic precedes its RED, and all REDs have
            // applied -> resetting pool + accumulator here is safe.
            asm volatile("st.relaxed.gpu.global.u64 [%0], %1;"
                         :: "l"(&g_acc), "l"(0ULL) : "memory");
            asm volatile("st.relaxed.gpu.global.s32 [%0], %1;"
                         :: "l"(&g_pool), "r"(0) : "memory");
        }
    }
}

extern "C" void kernel_launch(void* const* d_in, const int* in_sizes, int n_in,
                              void* d_out, int out_size)
{
    const float* p = (const float*)d_in[0];
    const float* t = (const float*)d_in[1];
    const float* a = (const float*)d_in[2];
    float* out = (float*)d_out;

    cudaFuncSetAttribute(yolo_loss_kernel,
                         cudaFuncAttributeMaxDynamicSharedMemorySize, SMEM_BYTES);

    yolo_loss_kernel<<<GRID, THREADS, SMEM_BYTES>>>(p, t, a, out);
}